// round 14
// baseline (speedup 1.0000x reference)
#include <cuda_runtime.h>
#include <cuda_bf16.h>
#include <cstdint>
#include <cstddef>

#define N_NODES 50000
#define N_EDGES 800000
#define F 128
#define KCAT 256
#define NB_SCAN 49   // ceil(50000/1024)
#define HALF0_NODES 25088            // 196 gemm tiles * 128
#define HALF0_BLOCKS 196
#define HALF1_BLOCKS 195             // rows 25088..50047

// ---------------------------------------------------------------------------
// Scratch (static device globals — no allocation)
// ---------------------------------------------------------------------------
__device__ int   g_counts[N_NODES];
__device__ int   g_rank[N_EDGES];                // within-dst rank of each edge
__device__ int   g_offsets[N_NODES + 1];         // block-LOCAL exclusive offsets
__device__ int   g_bsum[NB_SCAN];                // per-scan-block sums
__device__ int2  g_pairs[N_EDGES];               // {src, bitcast(weight)} CSR by dst
__device__ float g_aggmean[(size_t)N_NODES * F]; // segsum(w*h[src]) / wsum
__device__ float g_has[N_NODES];                 // 1 if node has incoming edges
__device__ float g_qbw[F];                       // Ww2 @ Qb
__device__ __nv_bfloat16 g_Bhi[F * KCAT];        // combined weight, bf16 hi
__device__ __nv_bfloat16 g_Blo[F * KCAT];        // combined weight, bf16 lo

// ---------------------------------------------------------------------------
// Histogram of dst + per-edge rank (x4 coarsened; N_EDGES % 4 == 0)
// ---------------------------------------------------------------------------
__global__ void hist_kernel(const int* __restrict__ dst) {
    int e0 = (blockIdx.x * blockDim.x + threadIdx.x) * 4;
    if (e0 < N_EDGES) {
        int4 d = *reinterpret_cast<const int4*>(&dst[e0]);
        int4 r;
        r.x = atomicAdd(&g_counts[d.x], 1);
        r.y = atomicAdd(&g_counts[d.y], 1);
        r.z = atomicAdd(&g_counts[d.z], 1);
        r.w = atomicAdd(&g_counts[d.w], 1);
        *reinterpret_cast<int4*>(&g_rank[e0]) = r;
    }
}

// ---------------------------------------------------------------------------
// Scan stage A: warp-shfl two-level block scan; offsets stay block-local.
// ---------------------------------------------------------------------------
__global__ __launch_bounds__(1024) void scanA_kernel() {
    __shared__ int wpart[32];
    int t = threadIdx.x;
    int lane = t & 31, wp = t >> 5;
    int i = blockIdx.x * 1024 + t;
    int v = (i < N_NODES) ? g_counts[i] : 0;
    int x = v;
#pragma unroll
    for (int o = 1; o < 32; o <<= 1) {
        int y = __shfl_up_sync(0xffffffffu, x, o);
        if (lane >= o) x += y;
    }
    if (lane == 31) wpart[wp] = x;
    __syncthreads();
    if (wp == 0) {
        int pv = wpart[lane];
        int px = pv;
#pragma unroll
        for (int o = 1; o < 32; o <<= 1) {
            int y = __shfl_up_sync(0xffffffffu, px, o);
            if (lane >= o) px += y;
        }
        wpart[lane] = px - pv;   // exclusive warp base
    }
    __syncthreads();
    int incl = x + wpart[wp];
    if (i < N_NODES) g_offsets[i] = incl - v;
    if (i == N_NODES - 1) g_offsets[N_NODES] = incl;  // raw inclusive (same block)
    if (t == 1023) g_bsum[blockIdx.x] = incl;
}

// ---------------------------------------------------------------------------
// In-CTA redundant exclusive scan of the 49 block sums -> smem spref[64].
// ---------------------------------------------------------------------------
__device__ __forceinline__ void compute_spref(int* spref) {
    int t = threadIdx.x;
    if (t < 32) {
        int v0 = g_bsum[t];
        int x0 = v0;
#pragma unroll
        for (int o = 1; o < 32; o <<= 1) {
            int y = __shfl_up_sync(0xffffffffu, x0, o);
            if (t >= o) x0 += y;
        }
        int tot0 = __shfl_sync(0xffffffffu, x0, 31);
        int i1 = 32 + t;
        int v1 = (i1 < NB_SCAN) ? g_bsum[i1] : 0;
        int x1 = v1;
#pragma unroll
        for (int o = 1; o < 32; o <<= 1) {
            int y = __shfl_up_sync(0xffffffffu, x1, o);
            if (t >= o) x1 += y;
        }
        spref[t] = x0 - v0;
        spref[i1] = x1 + tot0 - v1;
    }
    __syncthreads();
}

// ---------------------------------------------------------------------------
// Bucket-build: atomic-free, pos = local_off[dst] + spref[dst>>10] + rank[e]
// ---------------------------------------------------------------------------
__global__ void build_kernel(const int* __restrict__ src, const int* __restrict__ dst,
                             const float* __restrict__ w) {
    __shared__ int spref[64];
    compute_spref(spref);
    int e0 = (blockIdx.x * blockDim.x + threadIdx.x) * 4;
    if (e0 < N_EDGES) {
        int4   d = *reinterpret_cast<const int4*>(&dst[e0]);
        int4   s = *reinterpret_cast<const int4*>(&src[e0]);
        float4 x = *reinterpret_cast<const float4*>(&w[e0]);
        int4   r = *reinterpret_cast<const int4*>(&g_rank[e0]);
        int p0 = g_offsets[d.x] + spref[d.x >> 10] + r.x;
        int p1 = g_offsets[d.y] + spref[d.y >> 10] + r.y;
        int p2 = g_offsets[d.z] + spref[d.z >> 10] + r.z;
        int p3 = g_offsets[d.w] + spref[d.w >> 10] + r.w;
        g_pairs[p0] = make_int2(s.x, __float_as_int(x.x));
        g_pairs[p1] = make_int2(s.y, __float_as_int(x.y));
        g_pairs[p2] = make_int2(s.z, __float_as_int(x.z));
        g_pairs[p3] = make_int2(s.w, __float_as_int(x.w));
    }
}

// ---------------------------------------------------------------------------
// Fused Qc + weight prep, split-K parallel (block 512 = 4 segs x 128 cols)
// ---------------------------------------------------------------------------
__global__ __launch_bounds__(512) void qcprep_kernel(const float* __restrict__ Qw,
                                                     const float* __restrict__ Qb,
                                                     const float* __restrict__ Ww) {
    __shared__ float wrow[F];
    __shared__ float part[F];
    __shared__ float partial[4][F];
    const int o = blockIdx.x;
    const int tid = threadIdx.x;
    const int col = tid & 127;
    const int seg = tid >> 7;           // 0..3

    if (seg == 0) {
        float w2 = Ww[(size_t)o * KCAT + F + col];
        wrow[col] = w2;
        part[col] = w2 * Qb[col];
    }
    __syncthreads();

    float s = 0.0f;
    const int k0 = seg * 32;
#pragma unroll 8
    for (int k = k0; k < k0 + 32; k++)
        s += wrow[k] * Qw[(size_t)k * F + col];
    partial[seg][col] = s;
    __syncthreads();

    if (seg == 0) {
        float sum = partial[0][col] + partial[1][col] + partial[2][col] + partial[3][col];
        __nv_bfloat16 hi2 = __float2bfloat16(sum);
        g_Bhi[o * KCAT + F + col] = hi2;
        g_Blo[o * KCAT + F + col] = __float2bfloat16(sum - __bfloat162float(hi2));
        float w1 = Ww[(size_t)o * KCAT + col];
        __nv_bfloat16 hi1 = __float2bfloat16(w1);
        g_Bhi[o * KCAT + col] = hi1;
        g_Blo[o * KCAT + col] = __float2bfloat16(w1 - __bfloat162float(hi1));
    } else if (seg == 1 && col < 32) {
        int lane = col;
        float qb = part[lane] + part[lane + 32] + part[lane + 64] + part[lane + 96];
#pragma unroll
        for (int off = 16; off > 0; off >>= 1)
            qb += __shfl_xor_sync(0xffffffffu, qb, off);
        if (lane == 0) g_qbw[o] = qb;
    }
}

// ---------------------------------------------------------------------------
// Warp-per-node aggregation over node range [node0, node_end)
// ---------------------------------------------------------------------------
__global__ __launch_bounds__(256) void agg_kernel(const float* __restrict__ h,
                                                  int node0, int node_end) {
    __shared__ int spref[64];
    compute_spref(spref);

    int warp = ((blockIdx.x * blockDim.x + threadIdx.x) >> 5) + node0;
    int lane = threadIdx.x & 31;
    if (warp >= node_end) return;

    int j0 = g_offsets[warp] + spref[warp >> 10];
    int j1 = g_offsets[warp + 1] + spref[(warp + 1) >> 10];

    float4 acc = make_float4(0.f, 0.f, 0.f, 0.f);
    float wsum = 0.0f;

    for (int base = j0; base < j1; base += 32) {
        int m = j1 - base; if (m > 32) m = 32;
        int2 p = (lane < m) ? g_pairs[base + lane] : make_int2(0, 0);
#pragma unroll 4
        for (int t = 0; t < m; t++) {
            int s = __shfl_sync(0xffffffffu, p.x, t);
            float we = __int_as_float(__shfl_sync(0xffffffffu, p.y, t));
            float4 v = *reinterpret_cast<const float4*>(&h[(size_t)s * F + lane * 4]);
            acc.x += we * v.x;
            acc.y += we * v.y;
            acc.z += we * v.z;
            acc.w += we * v.w;
            wsum += we;
        }
    }

    float winv = (wsum == 0.0f) ? 1.0f : 1.0f / wsum;
    acc.x *= winv; acc.y *= winv; acc.z *= winv; acc.w *= winv;
    *reinterpret_cast<float4*>(&g_aggmean[(size_t)warp * F + lane * 4]) = acc;
    if (lane == 0) g_has[warp] = (wsum != 0.0f) ? 1.0f : 0.0f;
}

// ---------------------------------------------------------------------------
// HMMA (mma.sync bf16x3) GEMM + epilogue (R7 proven config), block offset blk0
// ---------------------------------------------------------------------------
#define ASTRIDE 72                      // halves per row (64 + 8 pad)
#define TILE_HALVES (128 * ASTRIDE)     // 9216 halves = 18432 B
#define SM_AHI 0
#define SM_ALO (SM_AHI + TILE_HALVES * 2)
#define SM_BHI (SM_ALO + TILE_HALVES * 2)
#define SM_BLO (SM_BHI + TILE_HALVES * 2)
#define SM_TILES_END (SM_BLO + TILE_HALVES * 2)   // 73728
#define STG_STRIDE 132                  // floats per staged row
#define SM_WB  SM_TILES_END             // 512 B
#define SM_QBW (SM_WB + 512)            // 512 B
#define SM_TOTAL (SM_QBW + 512)         // 74752 B (stage reuses tile region)

__device__ __forceinline__ void mma_bf16(float& d0, float& d1, float& d2, float& d3,
                                         uint32_t a0, uint32_t a1, uint32_t a2, uint32_t a3,
                                         uint32_t b0, uint32_t b1) {
    asm volatile(
        "mma.sync.aligned.m16n8k16.row.col.f32.bf16.bf16.f32 "
        "{%0,%1,%2,%3}, {%4,%5,%6,%7}, {%8,%9}, {%0,%1,%2,%3};"
        : "+f"(d0), "+f"(d1), "+f"(d2), "+f"(d3)
        : "r"(a0), "r"(a1), "r"(a2), "r"(a3), "r"(b0), "r"(b1));
}

__global__ __launch_bounds__(256) void mmagemm_kernel(
    const float* __restrict__ h, const float* __restrict__ Wb,
    float* __restrict__ out, int blk0)
{
    extern __shared__ char smem[];
    __nv_bfloat16* sAhi = (__nv_bfloat16*)(smem + SM_AHI);
    __nv_bfloat16* sAlo = (__nv_bfloat16*)(smem + SM_ALO);
    __nv_bfloat16* sBhi = (__nv_bfloat16*)(smem + SM_BHI);
    __nv_bfloat16* sBlo = (__nv_bfloat16*)(smem + SM_BLO);
    float* sStage = (float*)(smem + SM_AHI);          // reused after mainloop
    float* sWb    = (float*)(smem + SM_WB);
    float* sQbw   = (float*)(smem + SM_QBW);

    const int tid  = threadIdx.x;
    const int wid  = tid >> 5;
    const int lane = tid & 31;
    const int row0 = (blockIdx.x + blk0) * 128;

    if (tid < 128) {
        sWb[tid]  = Wb[tid];
        sQbw[tid] = g_qbw[tid];
    }

    const int m0 = (wid & 1) * 64;
    const int n0 = (wid >> 1) * 32;
    const int qrow = lane >> 2;
    const int qcol = (lane & 3) * 2;

    float acc[4][4][4];
#pragma unroll
    for (int mt = 0; mt < 4; mt++)
#pragma unroll
        for (int nt = 0; nt < 4; nt++)
#pragma unroll
            for (int r = 0; r < 4; r++) acc[mt][nt][r] = 0.0f;

    const int ar  = tid >> 1;
    const int acb = (tid & 1) * 32;
    const int grow_a = row0 + ar;
    const bool valid_a = (grow_a < N_NODES);

    for (int c = 0; c < 4; c++) {
        __syncthreads();
        // ---- A tile: fp32 -> bf16 hi/lo split ----
        {
            const float* srcp = (c < 2) ? h : g_aggmean;
            const int colofs = (c & 1) * 64;
            const float* rowp = srcp + (size_t)grow_a * F + colofs + acb;
            __nv_bfloat16* dhi = &sAhi[ar * ASTRIDE + acb];
            __nv_bfloat16* dlo = &sAlo[ar * ASTRIDE + acb];
#pragma unroll
            for (int j = 0; j < 8; j++) {
                float4 x = valid_a ? *reinterpret_cast<const float4*>(rowp + j * 4)
                                   : make_float4(0.f, 0.f, 0.f, 0.f);
                __nv_bfloat16 h0 = __float2bfloat16(x.x);
                __nv_bfloat16 h1 = __float2bfloat16(x.y);
                __nv_bfloat16 h2 = __float2bfloat16(x.z);
                __nv_bfloat16 h3 = __float2bfloat16(x.w);
                __nv_bfloat162 hp0(h0, h1), hp1(h2, h3);
                __nv_bfloat162 lp0 = __floats2bfloat162_rn(x.x - __bfloat162float(h0),
                                                           x.y - __bfloat162float(h1));
                __nv_bfloat162 lp1 = __floats2bfloat162_rn(x.z - __bfloat162float(h2),
                                                           x.w - __bfloat162float(h3));
                *reinterpret_cast<uint2*>(dhi + j * 4) =
                    make_uint2(*(uint32_t*)&hp0, *(uint32_t*)&hp1);
                *reinterpret_cast<uint2*>(dlo + j * 4) =
                    make_uint2(*(uint32_t*)&lp0, *(uint32_t*)&lp1);
            }
        }
        // ---- B tile: copy precomputed bf16 hi/lo ----
        {
            const int n  = tid >> 1;
            const int kb = (tid & 1) * 32;
            const size_t gofs = (size_t)n * KCAT + c * 64 + kb;
            const int sofs = n * ASTRIDE + kb;
#pragma unroll
            for (int j = 0; j < 4; j++) {
                *reinterpret_cast<uint4*>(&sBhi[sofs + j * 8]) =
                    *reinterpret_cast<const uint4*>(&g_Bhi[gofs + j * 8]);
                *reinterpret_cast<uint4*>(&sBlo[sofs + j * 8]) =
                    *reinterpret_cast<const uint4*>(&g_Blo[gofs + j * 8]);
            }
        }
        __syncthreads();

        // ---- compute: 3 splits x 4 k-steps x 16 mma ----
#pragma unroll
        for (int s = 0; s < 3; s++) {
            const __nv_bfloat16* pA = (s == 2) ? sAlo : sAhi;
            const __nv_bfloat16* pB = (s == 1) ? sBlo : sBhi;
#pragma unroll
            for (int ks = 0; ks < 4; ks++) {
                const int k0 = ks * 16;
                uint32_t bf[4][2];
#pragma unroll
                for (int nt = 0; nt < 4; nt++) {
                    const __nv_bfloat16* bp =
                        pB + (n0 + nt * 8 + qrow) * ASTRIDE + k0 + qcol;
                    bf[nt][0] = *reinterpret_cast<const uint32_t*>(bp);
                    bf[nt][1] = *reinterpret_cast<const uint32_t*>(bp + 8);
                }
                uint32_t af[4][4];
#pragma unroll
                for (int mt = 0; mt < 4; mt++) {
                    const __nv_bfloat16* ap =
                        pA + (m0 + mt * 16 + qrow) * ASTRIDE + k0 + qcol;
                    af[mt][0] = *reinterpret_cast<const uint32_t*>(ap);
                    af[mt][1] = *reinterpret_cast<const uint32_t*>(ap + 8 * ASTRIDE);
                    af[mt][2] = *reinterpret_cast<const uint32_t*>(ap + 8);
                    af[mt][3] = *reinterpret_cast<const uint32_t*>(ap + 8 * ASTRIDE + 8);
                }
#pragma unroll
                for (int mt = 0; mt < 4; mt++)
#pragma unroll
                    for (int nt = 0; nt < 4; nt++)
                        mma_bf16(acc[mt][nt][0], acc[mt][nt][1],
                                 acc[mt][nt][2], acc[mt][nt][3],
                                 af[mt][0], af[mt][1], af[mt][2], af[mt][3],
                                 bf[nt][0], bf[nt][1]);
            }
        }
    }

    // ---- stage accumulators to smem (reuse tile region) ----
    __syncthreads();
#pragma unroll
    for (int mt = 0; mt < 4; mt++) {
        const int r = m0 + mt * 16 + qrow;
#pragma unroll
        for (int nt = 0; nt < 4; nt++) {
            const int ccol = n0 + nt * 8 + qcol;
            *reinterpret_cast<float2*>(&sStage[r * STG_STRIDE + ccol]) =
                make_float2(acc[mt][nt][0], acc[mt][nt][1]);
            *reinterpret_cast<float2*>(&sStage[(r + 8) * STG_STRIDE + ccol]) =
                make_float2(acc[mt][nt][2], acc[mt][nt][3]);
        }
    }
    __syncthreads();

    // ---- epilogue: bias + leaky + L2 norm; thread owns half a row ----
    {
        const int r = tid >> 1;
        const int cb = (tid & 1) * 64;
        const int grow = row0 + r;
        const bool valid = (grow < N_NODES);
        const float hasv = valid ? g_has[grow] : 0.0f;

        float vals[64];
        float sq = 0.0f;
#pragma unroll
        for (int j = 0; j < 16; j++) {
            float4 x = *reinterpret_cast<const float4*>(&sStage[r * STG_STRIDE + cb + j * 4]);
            float v0 = x.x + sWb[cb + j*4 + 0] + hasv * sQbw[cb + j*4 + 0];
            float v1 = x.y + sWb[cb + j*4 + 1] + hasv * sQbw[cb + j*4 + 1];
            float v2 = x.z + sWb[cb + j*4 + 2] + hasv * sQbw[cb + j*4 + 2];
            float v3 = x.w + sWb[cb + j*4 + 3] + hasv * sQbw[cb + j*4 + 3];
            v0 = (v0 > 0.0f) ? v0 : 0.01f * v0;
            v1 = (v1 > 0.0f) ? v1 : 0.01f * v1;
            v2 = (v2 > 0.0f) ? v2 : 0.01f * v2;
            v3 = (v3 > 0.0f) ? v3 : 0.01f * v3;
            vals[j*4+0] = v0; vals[j*4+1] = v1; vals[j*4+2] = v2; vals[j*4+3] = v3;
            sq += v0 * v0 + v1 * v1 + v2 * v2 + v3 * v3;
        }
        sq += __shfl_xor_sync(0xffffffffu, sq, 1);
        float nrm = sqrtf(sq);
        float inv = (nrm == 0.0f) ? 1.0f : 1.0f / nrm;

        if (valid) {
#pragma unroll
            for (int j = 0; j < 16; j++) {
                float4 o;
                o.x = vals[j*4+0] * inv;
                o.y = vals[j*4+1] * inv;
                o.z = vals[j*4+2] * inv;
                o.w = vals[j*4+3] * inv;
                *reinterpret_cast<float4*>(&out[(size_t)grow * F + cb + j * 4]) = o;
            }
        }
    }
}

// ---------------------------------------------------------------------------
// Launch — 2-stream fork/join (graph-capturable via event edges)
// Inputs: 0:h 1:ppr_weight 2:Qw 3:Qb 4:Ww 5:Wb 6:src 7:dst
// ---------------------------------------------------------------------------
extern "C" void kernel_launch(void* const* d_in, const int* in_sizes, int n_in,
                              void* d_out, int out_size) {
    const float* h   = (const float*)d_in[0];
    const float* ppr = (const float*)d_in[1];
    const float* Qw  = (const float*)d_in[2];
    const float* Qb  = (const float*)d_in[3];
    const float* Ww  = (const float*)d_in[4];
    const float* Wb  = (const float*)d_in[5];
    const int*   src = (const int*)d_in[6];
    const int*   dst = (const int*)d_in[7];
    float* out = (float*)d_out;

    static cudaStream_t s1 = nullptr;
    static cudaEvent_t evStart = nullptr, evA0 = nullptr, evA1 = nullptr, evG = nullptr;
    if (s1 == nullptr) {
        cudaStreamCreateWithFlags(&s1, cudaStreamNonBlocking);
        cudaEventCreateWithFlags(&evStart, cudaEventDisableTiming);
        cudaEventCreateWithFlags(&evA0, cudaEventDisableTiming);
        cudaEventCreateWithFlags(&evA1, cudaEventDisableTiming);
        cudaEventCreateWithFlags(&evG, cudaEventDisableTiming);
        cudaFuncSetAttribute(mmagemm_kernel,
                             cudaFuncAttributeMaxDynamicSharedMemorySize, SM_TOTAL);
    }

    void* counts_ptr = nullptr;
    cudaGetSymbolAddress(&counts_ptr, g_counts);
    cudaMemsetAsync(counts_ptr, 0, N_NODES * sizeof(int), 0);

    // fork: side stream runs qcprep concurrently with the CSR chain
    cudaEventRecord(evStart, 0);
    cudaStreamWaitEvent(s1, evStart, 0);
    qcprep_kernel<<<F, 512, 0, s1>>>(Qw, Qb, Ww);

    const int EQ4 = N_EDGES / 4;   // 200000
    hist_kernel <<<(EQ4 + 255) / 256, 256>>>(dst);
    scanA_kernel<<<NB_SCAN, 1024>>>();
    build_kernel<<<(EQ4 + 255) / 256, 256>>>(src, dst, ppr);

    // agg half 0 -> event -> agg half 1 (main stream)
    agg_kernel<<<HALF0_NODES / 8, 256>>>(h, 0, HALF0_NODES);
    cudaEventRecord(evA0, 0);
    agg_kernel<<<(N_NODES - HALF0_NODES + 7) / 8, 256>>>(h, HALF0_NODES, N_NODES);
    cudaEventRecord(evA1, 0);

    // side stream: gemm half 0 overlaps agg half 1; then gemm half 1
    cudaStreamWaitEvent(s1, evA0, 0);
    mmagemm_kernel<<<HALF0_BLOCKS, 256, SM_TOTAL, s1>>>(h, Wb, out, 0);
    cudaStreamWaitEvent(s1, evA1, 0);
    mmagemm_kernel<<<HALF1_BLOCKS, 256, SM_TOTAL, s1>>>(h, Wb, out, HALF0_BLOCKS);
    cudaEventRecord(evG, s1);

    // join back to main stream
    cudaStreamWaitEvent(0, evG, 0);
}

// round 15
// speedup vs baseline: 1.1914x; 1.1914x over previous
#include <cuda_runtime.h>
#include <cuda_bf16.h>
#include <cstdint>
#include <cstddef>

#define N_NODES 50000
#define N_EDGES 800000
#define F 128
#define KCAT 256
#define NB_SCAN 49   // ceil(50000/1024)

// ---------------------------------------------------------------------------
// Scratch (static device globals — no allocation)
// ---------------------------------------------------------------------------
__device__ int   g_counts[N_NODES];
__device__ int   g_rank[N_EDGES];                // within-dst rank of each edge
__device__ int   g_offsets[N_NODES + 1];         // block-LOCAL exclusive offsets
__device__ int   g_bsum[NB_SCAN];                // per-scan-block sums
__device__ int2  g_pairs[N_EDGES];               // {src, bitcast(weight)} CSR by dst
__device__ float g_aggmean[(size_t)N_NODES * F]; // segsum(w*h[src]) / wsum
__device__ float g_has[N_NODES];                 // 1 if node has incoming edges
__device__ float g_qbw[F];                       // Ww2 @ Qb
__device__ __nv_bfloat16 g_Bhi[F * KCAT];        // combined weight, bf16 hi
__device__ __nv_bfloat16 g_Blo[F * KCAT];        // combined weight, bf16 lo

// ---------------------------------------------------------------------------
// Histogram of dst + per-edge rank (x4 coarsened; N_EDGES % 4 == 0)
// ---------------------------------------------------------------------------
__global__ void hist_kernel(const int* __restrict__ dst) {
    int e0 = (blockIdx.x * blockDim.x + threadIdx.x) * 4;
    if (e0 < N_EDGES) {
        int4 d = *reinterpret_cast<const int4*>(&dst[e0]);
        int4 r;
        r.x = atomicAdd(&g_counts[d.x], 1);
        r.y = atomicAdd(&g_counts[d.y], 1);
        r.z = atomicAdd(&g_counts[d.z], 1);
        r.w = atomicAdd(&g_counts[d.w], 1);
        *reinterpret_cast<int4*>(&g_rank[e0]) = r;
    }
}

// ---------------------------------------------------------------------------
// Scan stage A: warp-shfl two-level block scan; offsets stay block-local.
// ---------------------------------------------------------------------------
__global__ __launch_bounds__(1024) void scanA_kernel() {
    __shared__ int wpart[32];
    int t = threadIdx.x;
    int lane = t & 31, wp = t >> 5;
    int i = blockIdx.x * 1024 + t;
    int v = (i < N_NODES) ? g_counts[i] : 0;
    int x = v;
#pragma unroll
    for (int o = 1; o < 32; o <<= 1) {
        int y = __shfl_up_sync(0xffffffffu, x, o);
        if (lane >= o) x += y;
    }
    if (lane == 31) wpart[wp] = x;
    __syncthreads();
    if (wp == 0) {
        int pv = wpart[lane];
        int px = pv;
#pragma unroll
        for (int o = 1; o < 32; o <<= 1) {
            int y = __shfl_up_sync(0xffffffffu, px, o);
            if (lane >= o) px += y;
        }
        wpart[lane] = px - pv;   // exclusive warp base
    }
    __syncthreads();
    int incl = x + wpart[wp];
    if (i < N_NODES) g_offsets[i] = incl - v;
    if (i == N_NODES - 1) g_offsets[N_NODES] = incl;  // raw inclusive (same block)
    if (t == 1023) g_bsum[blockIdx.x] = incl;
}

// ---------------------------------------------------------------------------
// In-CTA redundant exclusive scan of the 49 block sums -> smem spref[64].
// ---------------------------------------------------------------------------
__device__ __forceinline__ void compute_spref(int* spref) {
    int t = threadIdx.x;
    if (t < 32) {
        int v0 = g_bsum[t];
        int x0 = v0;
#pragma unroll
        for (int o = 1; o < 32; o <<= 1) {
            int y = __shfl_up_sync(0xffffffffu, x0, o);
            if (t >= o) x0 += y;
        }
        int tot0 = __shfl_sync(0xffffffffu, x0, 31);
        int i1 = 32 + t;
        int v1 = (i1 < NB_SCAN) ? g_bsum[i1] : 0;
        int x1 = v1;
#pragma unroll
        for (int o = 1; o < 32; o <<= 1) {
            int y = __shfl_up_sync(0xffffffffu, x1, o);
            if (t >= o) x1 += y;
        }
        spref[t] = x0 - v0;
        spref[i1] = x1 + tot0 - v1;
    }
    __syncthreads();
}

// ---------------------------------------------------------------------------
// Bucket-build: atomic-free, pos = local_off[dst] + spref[dst>>10] + rank[e]
// ---------------------------------------------------------------------------
__global__ void build_kernel(const int* __restrict__ src, const int* __restrict__ dst,
                             const float* __restrict__ w) {
    __shared__ int spref[64];
    compute_spref(spref);
    int e0 = (blockIdx.x * blockDim.x + threadIdx.x) * 4;
    if (e0 < N_EDGES) {
        int4   d = *reinterpret_cast<const int4*>(&dst[e0]);
        int4   s = *reinterpret_cast<const int4*>(&src[e0]);
        float4 x = *reinterpret_cast<const float4*>(&w[e0]);
        int4   r = *reinterpret_cast<const int4*>(&g_rank[e0]);
        int p0 = g_offsets[d.x] + spref[d.x >> 10] + r.x;
        int p1 = g_offsets[d.y] + spref[d.y >> 10] + r.y;
        int p2 = g_offsets[d.z] + spref[d.z >> 10] + r.z;
        int p3 = g_offsets[d.w] + spref[d.w >> 10] + r.w;
        g_pairs[p0] = make_int2(s.x, __float_as_int(x.x));
        g_pairs[p1] = make_int2(s.y, __float_as_int(x.y));
        g_pairs[p2] = make_int2(s.z, __float_as_int(x.z));
        g_pairs[p3] = make_int2(s.w, __float_as_int(x.w));
    }
}

// ---------------------------------------------------------------------------
// Fused Qc + weight prep, split-K parallel (block 512 = 4 segs x 128 cols)
// ---------------------------------------------------------------------------
__global__ __launch_bounds__(512) void qcprep_kernel(const float* __restrict__ Qw,
                                                     const float* __restrict__ Qb,
                                                     const float* __restrict__ Ww) {
    __shared__ float wrow[F];
    __shared__ float part[F];
    __shared__ float partial[4][F];
    const int o = blockIdx.x;
    const int tid = threadIdx.x;
    const int col = tid & 127;
    const int seg = tid >> 7;           // 0..3

    if (seg == 0) {
        float w2 = Ww[(size_t)o * KCAT + F + col];
        wrow[col] = w2;
        part[col] = w2 * Qb[col];
    }
    __syncthreads();

    float s = 0.0f;
    const int k0 = seg * 32;
#pragma unroll 8
    for (int k = k0; k < k0 + 32; k++)
        s += wrow[k] * Qw[(size_t)k * F + col];
    partial[seg][col] = s;
    __syncthreads();

    if (seg == 0) {
        float sum = partial[0][col] + partial[1][col] + partial[2][col] + partial[3][col];
        __nv_bfloat16 hi2 = __float2bfloat16(sum);
        g_Bhi[o * KCAT + F + col] = hi2;
        g_Blo[o * KCAT + F + col] = __float2bfloat16(sum - __bfloat162float(hi2));
        float w1 = Ww[(size_t)o * KCAT + col];
        __nv_bfloat16 hi1 = __float2bfloat16(w1);
        g_Bhi[o * KCAT + col] = hi1;
        g_Blo[o * KCAT + col] = __float2bfloat16(w1 - __bfloat162float(hi1));
    } else if (seg == 1 && col < 32) {
        int lane = col;
        float qb = part[lane] + part[lane + 32] + part[lane + 64] + part[lane + 96];
#pragma unroll
        for (int off = 16; off > 0; off >>= 1)
            qb += __shfl_xor_sync(0xffffffffu, qb, off);
        if (lane == 0) g_qbw[o] = qb;
    }
}

// ---------------------------------------------------------------------------
// Warp-per-node aggregation: aggmean[n] = (sum_e w_e * h[src_e]) / wsum
// ---------------------------------------------------------------------------
__global__ __launch_bounds__(256) void agg_kernel(const float* __restrict__ h) {
    __shared__ int spref[64];
    compute_spref(spref);

    int warp = (blockIdx.x * blockDim.x + threadIdx.x) >> 5;
    int lane = threadIdx.x & 31;
    if (warp >= N_NODES) return;

    int j0 = g_offsets[warp] + spref[warp >> 10];
    int j1 = g_offsets[warp + 1] + spref[(warp + 1) >> 10];

    float4 acc = make_float4(0.f, 0.f, 0.f, 0.f);
    float wsum = 0.0f;

    for (int base = j0; base < j1; base += 32) {
        int m = j1 - base; if (m > 32) m = 32;
        int2 p = (lane < m) ? g_pairs[base + lane] : make_int2(0, 0);
#pragma unroll 4
        for (int t = 0; t < m; t++) {
            int s = __shfl_sync(0xffffffffu, p.x, t);
            float we = __int_as_float(__shfl_sync(0xffffffffu, p.y, t));
            float4 v = *reinterpret_cast<const float4*>(&h[(size_t)s * F + lane * 4]);
            acc.x += we * v.x;
            acc.y += we * v.y;
            acc.z += we * v.z;
            acc.w += we * v.w;
            wsum += we;
        }
    }

    float winv = (wsum == 0.0f) ? 1.0f : 1.0f / wsum;
    acc.x *= winv; acc.y *= winv; acc.z *= winv; acc.w *= winv;
    *reinterpret_cast<float4*>(&g_aggmean[(size_t)warp * F + lane * 4]) = acc;
    if (lane == 0) g_has[warp] = (wsum != 0.0f) ? 1.0f : 0.0f;
}

// ---------------------------------------------------------------------------
// HMMA (mma.sync bf16x3) GEMM + epilogue (R7 proven config):
//   out = l2norm(leaky(concat[h, aggmean] @ W^T + Wb + has*qbw))
// CTA tile: M=128, N=128, K=256 in 4 chunks of 64.
// ---------------------------------------------------------------------------
#define ASTRIDE 72                      // halves per row (64 + 8 pad)
#define TILE_HALVES (128 * ASTRIDE)     // 9216 halves = 18432 B
#define SM_AHI 0
#define SM_ALO (SM_AHI + TILE_HALVES * 2)
#define SM_BHI (SM_ALO + TILE_HALVES * 2)
#define SM_BLO (SM_BHI + TILE_HALVES * 2)
#define SM_TILES_END (SM_BLO + TILE_HALVES * 2)   // 73728
#define STG_STRIDE 132                  // floats per staged row
#define SM_WB  SM_TILES_END             // 512 B
#define SM_QBW (SM_WB + 512)            // 512 B
#define SM_TOTAL (SM_QBW + 512)         // 74752 B (stage reuses tile region)

__device__ __forceinline__ void mma_bf16(float& d0, float& d1, float& d2, float& d3,
                                         uint32_t a0, uint32_t a1, uint32_t a2, uint32_t a3,
                                         uint32_t b0, uint32_t b1) {
    asm volatile(
        "mma.sync.aligned.m16n8k16.row.col.f32.bf16.bf16.f32 "
        "{%0,%1,%2,%3}, {%4,%5,%6,%7}, {%8,%9}, {%0,%1,%2,%3};"
        : "+f"(d0), "+f"(d1), "+f"(d2), "+f"(d3)
        : "r"(a0), "r"(a1), "r"(a2), "r"(a3), "r"(b0), "r"(b1));
}

__global__ __launch_bounds__(256) void mmagemm_kernel(
    const float* __restrict__ h, const float* __restrict__ Wb,
    float* __restrict__ out)
{
    extern __shared__ char smem[];
    __nv_bfloat16* sAhi = (__nv_bfloat16*)(smem + SM_AHI);
    __nv_bfloat16* sAlo = (__nv_bfloat16*)(smem + SM_ALO);
    __nv_bfloat16* sBhi = (__nv_bfloat16*)(smem + SM_BHI);
    __nv_bfloat16* sBlo = (__nv_bfloat16*)(smem + SM_BLO);
    float* sStage = (float*)(smem + SM_AHI);          // reused after mainloop
    float* sWb    = (float*)(smem + SM_WB);
    float* sQbw   = (float*)(smem + SM_QBW);

    const int tid  = threadIdx.x;
    const int wid  = tid >> 5;
    const int lane = tid & 31;
    const int row0 = blockIdx.x * 128;

    if (tid < 128) {
        sWb[tid]  = Wb[tid];
        sQbw[tid] = g_qbw[tid];
    }

    const int m0 = (wid & 1) * 64;
    const int n0 = (wid >> 1) * 32;
    const int qrow = lane >> 2;
    const int qcol = (lane & 3) * 2;

    float acc[4][4][4];
#pragma unroll
    for (int mt = 0; mt < 4; mt++)
#pragma unroll
        for (int nt = 0; nt < 4; nt++)
#pragma unroll
            for (int r = 0; r < 4; r++) acc[mt][nt][r] = 0.0f;

    const int ar  = tid >> 1;
    const int acb = (tid & 1) * 32;
    const int grow_a = row0 + ar;
    const bool valid_a = (grow_a < N_NODES);

    for (int c = 0; c < 4; c++) {
        __syncthreads();
        // ---- A tile: fp32 -> bf16 hi/lo split ----
        {
            const float* srcp = (c < 2) ? h : g_aggmean;
            const int colofs = (c & 1) * 64;
            const float* rowp = srcp + (size_t)grow_a * F + colofs + acb;
            __nv_bfloat16* dhi = &sAhi[ar * ASTRIDE + acb];
            __nv_bfloat16* dlo = &sAlo[ar * ASTRIDE + acb];
#pragma unroll
            for (int j = 0; j < 8; j++) {
                float4 x = valid_a ? *reinterpret_cast<const float4*>(rowp + j * 4)
                                   : make_float4(0.f, 0.f, 0.f, 0.f);
                __nv_bfloat16 h0 = __float2bfloat16(x.x);
                __nv_bfloat16 h1 = __float2bfloat16(x.y);
                __nv_bfloat16 h2 = __float2bfloat16(x.z);
                __nv_bfloat16 h3 = __float2bfloat16(x.w);
                __nv_bfloat162 hp0(h0, h1), hp1(h2, h3);
                __nv_bfloat162 lp0 = __floats2bfloat162_rn(x.x - __bfloat162float(h0),
                                                           x.y - __bfloat162float(h1));
                __nv_bfloat162 lp1 = __floats2bfloat162_rn(x.z - __bfloat162float(h2),
                                                           x.w - __bfloat162float(h3));
                *reinterpret_cast<uint2*>(dhi + j * 4) =
                    make_uint2(*(uint32_t*)&hp0, *(uint32_t*)&hp1);
                *reinterpret_cast<uint2*>(dlo + j * 4) =
                    make_uint2(*(uint32_t*)&lp0, *(uint32_t*)&lp1);
            }
        }
        // ---- B tile: copy precomputed bf16 hi/lo ----
        {
            const int n  = tid >> 1;
            const int kb = (tid & 1) * 32;
            const size_t gofs = (size_t)n * KCAT + c * 64 + kb;
            const int sofs = n * ASTRIDE + kb;
#pragma unroll
            for (int j = 0; j < 4; j++) {
                *reinterpret_cast<uint4*>(&sBhi[sofs + j * 8]) =
                    *reinterpret_cast<const uint4*>(&g_Bhi[gofs + j * 8]);
                *reinterpret_cast<uint4*>(&sBlo[sofs + j * 8]) =
                    *reinterpret_cast<const uint4*>(&g_Blo[gofs + j * 8]);
            }
        }
        __syncthreads();

        // ---- compute: 3 splits x 4 k-steps x 16 mma ----
#pragma unroll
        for (int s = 0; s < 3; s++) {
            const __nv_bfloat16* pA = (s == 2) ? sAlo : sAhi;
            const __nv_bfloat16* pB = (s == 1) ? sBlo : sBhi;
#pragma unroll
            for (int ks = 0; ks < 4; ks++) {
                const int k0 = ks * 16;
                uint32_t bf[4][2];
#pragma unroll
                for (int nt = 0; nt < 4; nt++) {
                    const __nv_bfloat16* bp =
                        pB + (n0 + nt * 8 + qrow) * ASTRIDE + k0 + qcol;
                    bf[nt][0] = *reinterpret_cast<const uint32_t*>(bp);
                    bf[nt][1] = *reinterpret_cast<const uint32_t*>(bp + 8);
                }
                uint32_t af[4][4];
#pragma unroll
                for (int mt = 0; mt < 4; mt++) {
                    const __nv_bfloat16* ap =
                        pA + (m0 + mt * 16 + qrow) * ASTRIDE + k0 + qcol;
                    af[mt][0] = *reinterpret_cast<const uint32_t*>(ap);
                    af[mt][1] = *reinterpret_cast<const uint32_t*>(ap + 8 * ASTRIDE);
                    af[mt][2] = *reinterpret_cast<const uint32_t*>(ap + 8);
                    af[mt][3] = *reinterpret_cast<const uint32_t*>(ap + 8 * ASTRIDE + 8);
                }
#pragma unroll
                for (int mt = 0; mt < 4; mt++)
#pragma unroll
                    for (int nt = 0; nt < 4; nt++)
                        mma_bf16(acc[mt][nt][0], acc[mt][nt][1],
                                 acc[mt][nt][2], acc[mt][nt][3],
                                 af[mt][0], af[mt][1], af[mt][2], af[mt][3],
                                 bf[nt][0], bf[nt][1]);
            }
        }
    }

    // ---- stage accumulators to smem (reuse tile region) ----
    __syncthreads();
#pragma unroll
    for (int mt = 0; mt < 4; mt++) {
        const int r = m0 + mt * 16 + qrow;
#pragma unroll
        for (int nt = 0; nt < 4; nt++) {
            const int ccol = n0 + nt * 8 + qcol;
            *reinterpret_cast<float2*>(&sStage[r * STG_STRIDE + ccol]) =
                make_float2(acc[mt][nt][0], acc[mt][nt][1]);
            *reinterpret_cast<float2*>(&sStage[(r + 8) * STG_STRIDE + ccol]) =
                make_float2(acc[mt][nt][2], acc[mt][nt][3]);
        }
    }
    __syncthreads();

    // ---- epilogue: bias + leaky + L2 norm; thread owns half a row ----
    {
        const int r = tid >> 1;
        const int cb = (tid & 1) * 64;
        const int grow = row0 + r;
        const bool valid = (grow < N_NODES);
        const float hasv = valid ? g_has[grow] : 0.0f;

        float vals[64];
        float sq = 0.0f;
#pragma unroll
        for (int j = 0; j < 16; j++) {
            float4 x = *reinterpret_cast<const float4*>(&sStage[r * STG_STRIDE + cb + j * 4]);
            float v0 = x.x + sWb[cb + j*4 + 0] + hasv * sQbw[cb + j*4 + 0];
            float v1 = x.y + sWb[cb + j*4 + 1] + hasv * sQbw[cb + j*4 + 1];
            float v2 = x.z + sWb[cb + j*4 + 2] + hasv * sQbw[cb + j*4 + 2];
            float v3 = x.w + sWb[cb + j*4 + 3] + hasv * sQbw[cb + j*4 + 3];
            v0 = (v0 > 0.0f) ? v0 : 0.01f * v0;
            v1 = (v1 > 0.0f) ? v1 : 0.01f * v1;
            v2 = (v2 > 0.0f) ? v2 : 0.01f * v2;
            v3 = (v3 > 0.0f) ? v3 : 0.01f * v3;
            vals[j*4+0] = v0; vals[j*4+1] = v1; vals[j*4+2] = v2; vals[j*4+3] = v3;
            sq += v0 * v0 + v1 * v1 + v2 * v2 + v3 * v3;
        }
        sq += __shfl_xor_sync(0xffffffffu, sq, 1);
        float nrm = sqrtf(sq);
        float inv = (nrm == 0.0f) ? 1.0f : 1.0f / nrm;

        if (valid) {
#pragma unroll
            for (int j = 0; j < 16; j++) {
                float4 o;
                o.x = vals[j*4+0] * inv;
                o.y = vals[j*4+1] * inv;
                o.z = vals[j*4+2] * inv;
                o.w = vals[j*4+3] * inv;
                *reinterpret_cast<float4*>(&out[(size_t)grow * F + cb + j * 4]) = o;
            }
        }
    }
}

// ---------------------------------------------------------------------------
// Launch — qcprep forked to side stream (hidden under CSR chain); single
// full-grid agg and gemm (no wave-quantization loss).
// Inputs: 0:h 1:ppr_weight 2:Qw 3:Qb 4:Ww 5:Wb 6:src 7:dst
// ---------------------------------------------------------------------------
extern "C" void kernel_launch(void* const* d_in, const int* in_sizes, int n_in,
                              void* d_out, int out_size) {
    const float* h   = (const float*)d_in[0];
    const float* ppr = (const float*)d_in[1];
    const float* Qw  = (const float*)d_in[2];
    const float* Qb  = (const float*)d_in[3];
    const float* Ww  = (const float*)d_in[4];
    const float* Wb  = (const float*)d_in[5];
    const int*   src = (const int*)d_in[6];
    const int*   dst = (const int*)d_in[7];
    float* out = (float*)d_out;

    static cudaStream_t s1 = nullptr;
    static cudaEvent_t evStart = nullptr, evQ = nullptr;
    if (s1 == nullptr) {
        cudaStreamCreateWithFlags(&s1, cudaStreamNonBlocking);
        cudaEventCreateWithFlags(&evStart, cudaEventDisableTiming);
        cudaEventCreateWithFlags(&evQ, cudaEventDisableTiming);
        cudaFuncSetAttribute(mmagemm_kernel,
                             cudaFuncAttributeMaxDynamicSharedMemorySize, SM_TOTAL);
    }

    void* counts_ptr = nullptr;
    cudaGetSymbolAddress(&counts_ptr, g_counts);
    cudaMemsetAsync(counts_ptr, 0, N_NODES * sizeof(int), 0);

    // fork: side stream runs qcprep concurrently with the CSR chain
    cudaEventRecord(evStart, 0);
    cudaStreamWaitEvent(s1, evStart, 0);
    qcprep_kernel<<<F, 512, 0, s1>>>(Qw, Qb, Ww);
    cudaEventRecord(evQ, s1);

    const int EQ4 = N_EDGES / 4;   // 200000
    hist_kernel <<<(EQ4 + 255) / 256, 256>>>(dst);
    scanA_kernel<<<NB_SCAN, 1024>>>();
    build_kernel<<<(EQ4 + 255) / 256, 256>>>(src, dst, ppr);
    agg_kernel  <<<(N_NODES + 7) / 8, 256>>>(h);

    // join: gemm needs qcprep's weights
    cudaStreamWaitEvent(0, evQ, 0);
    mmagemm_kernel<<<(N_NODES + 127) / 128, 256, SM_TOTAL>>>(h, Wb, out);
}